// round 3
// baseline (speedup 1.0000x reference)
#include <cuda_runtime.h>
#include <math.h>

#define BATCH 2
#define SEQ   2048
#define DIM   1024
#define HEADS 16
#define HDIM  64
#define MROWS (BATCH * SEQ)     /* 4096 */
#define NQKV  (3 * DIM)         /* 3072 */

// Scratch (device globals: no runtime allocation allowed)
__device__ float g_qkv[(size_t)MROWS * NQKV];   // ~50 MB
__device__ float g_att[(size_t)MROWS * DIM];    // ~17 MB

// ---------------------------------------------------------------------------
// helpers
// ---------------------------------------------------------------------------
__device__ __forceinline__ unsigned ldcvt(const float* p) {
    unsigned u;
    asm("cvt.rna.tf32.f32 %0, %1;" : "=r"(u) : "f"(*p));
    return u;
}

__device__ __forceinline__ void mma_tf32(float c[4], const unsigned a[4], const unsigned b[2]) {
    asm volatile(
        "mma.sync.aligned.m16n8k8.row.col.f32.tf32.tf32.f32 "
        "{%0,%1,%2,%3}, {%4,%5,%6,%7}, {%8,%9}, {%0,%1,%2,%3};\n"
        : "+f"(c[0]), "+f"(c[1]), "+f"(c[2]), "+f"(c[3])
        : "r"(a[0]), "r"(a[1]), "r"(a[2]), "r"(a[3]), "r"(b[0]), "r"(b[1]));
}

__device__ __forceinline__ void cp16(float* s, const float* g) {
    unsigned sa = (unsigned)__cvta_generic_to_shared(s);
    asm volatile("cp.async.cg.shared.global [%0], [%1], 16;\n" :: "r"(sa), "l"(g));
}
#define CP_COMMIT() asm volatile("cp.async.commit_group;\n" ::: "memory")
#define CP_WAIT(N)  asm volatile("cp.async.wait_group %0;\n" :: "n"(N) : "memory")

// ---------------------------------------------------------------------------
// TF32 GEMM: C[M,N] = A[M,K] @ W[K,N] + bias[N]
// Block 128x128x32, 8 warps (2x4), warp tile 64x32, mma m16n8k8.
// 3-stage cp.async pipeline, one barrier per K-iter.
// ---------------------------------------------------------------------------
#define BM 128
#define BN 128
#define BK 32
#define APITCH 36    /* conflict-free A-frag loads */
#define BPITCH 132   /* conflict-free B-frag loads */
#define GSTAGES 3
#define ASZ (BM * APITCH)
#define BSZ (BK * BPITCH)
#define GEMM_SMEM ((GSTAGES * (ASZ + BSZ)) * (int)sizeof(float))

__global__ __launch_bounds__(256, 1) void gemm_tf32_kernel(
    const float* __restrict__ A, const float* __restrict__ W,
    const float* __restrict__ bias, float* __restrict__ C,
    int M, int N, int K)
{
    extern __shared__ float dyn[];
    float* As = dyn;                     // [GSTAGES][BM][APITCH]
    float* Bs = dyn + GSTAGES * ASZ;     // [GSTAGES][BK][BPITCH]

    const int tid  = threadIdx.x;
    const int lane = tid & 31;
    const int warp = tid >> 5;
    const int wr   = warp >> 2;          // 0..1
    const int wc   = warp & 3;           // 0..3
    const int grp  = lane >> 2;          // 0..7
    const int qid  = lane & 3;           // 0..3

    const int m0 = blockIdx.y * BM;
    const int n0 = blockIdx.x * BN;

    const int arow = tid >> 3;           // 0..31 (rows arow + 32*i)
    const int akc  = (tid & 7) * 4;      // k offset within BK
    const int brow = tid >> 5;           // 0..7  (rows brow + 8*i)
    const int bnc  = (tid & 31) * 4;     // n offset within BN

    const int T = K / BK;

    // tile loader: global -> smem stage (raw fp32 via cp.async)
    auto loadtile = [&](int t) {
        float* as = As + (t % GSTAGES) * ASZ;
        float* bs = Bs + (t % GSTAGES) * BSZ;
        const int k0 = t * BK;
#pragma unroll
        for (int i = 0; i < 4; ++i)
            cp16(&as[(arow + 32 * i) * APITCH + akc],
                 A + (size_t)(m0 + arow + 32 * i) * K + k0 + akc);
#pragma unroll
        for (int i = 0; i < 4; ++i)
            cp16(&bs[(brow + 8 * i) * BPITCH + bnc],
                 W + (size_t)(k0 + brow + 8 * i) * N + n0 + bnc);
        CP_COMMIT();
    };

    float acc[4][4][4];
#pragma unroll
    for (int mi = 0; mi < 4; ++mi)
#pragma unroll
        for (int nj = 0; nj < 4; ++nj)
#pragma unroll
            for (int r = 0; r < 4; ++r) acc[mi][nj][r] = 0.f;

    loadtile(0);
    loadtile(1);

    for (int t = 0; t < T; ++t) {
        CP_WAIT(1);              // tile t resident (t+1 may still fly)
        __syncthreads();         // also protects stage (t-1)%3 for rewrite
        if (t + 2 < T) loadtile(t + 2);

        const float* as = As + (t % GSTAGES) * ASZ;
        const float* bs = Bs + (t % GSTAGES) * BSZ;

#pragma unroll
        for (int ks = 0; ks < 4; ++ks) {
            unsigned af[4][4], bf[4][2];
#pragma unroll
            for (int mi = 0; mi < 4; ++mi) {
                const float* base = &as[(wr * 64 + mi * 16 + grp) * APITCH + ks * 8 + qid];
                af[mi][0] = ldcvt(base);
                af[mi][1] = ldcvt(base + 8 * APITCH);
                af[mi][2] = ldcvt(base + 4);
                af[mi][3] = ldcvt(base + 8 * APITCH + 4);
            }
#pragma unroll
            for (int nj = 0; nj < 4; ++nj) {
                const float* base = &bs[(ks * 8 + qid) * BPITCH + wc * 32 + nj * 8 + grp];
                bf[nj][0] = ldcvt(base);
                bf[nj][1] = ldcvt(base + 4 * BPITCH);
            }
#pragma unroll
            for (int mi = 0; mi < 4; ++mi)
#pragma unroll
                for (int nj = 0; nj < 4; ++nj)
                    mma_tf32(acc[mi][nj], af[mi], bf[nj]);
        }
    }

    // epilogue: bias + store
#pragma unroll
    for (int mi = 0; mi < 4; ++mi) {
#pragma unroll
        for (int nj = 0; nj < 4; ++nj) {
            const int row = m0 + wr * 64 + mi * 16 + grp;
            const int col = n0 + wc * 32 + nj * 8 + 2 * qid;
            const float b0 = bias[col];
            const float b1 = bias[col + 1];
            float2 v0 = make_float2(acc[mi][nj][0] + b0, acc[mi][nj][1] + b1);
            float2 v1 = make_float2(acc[mi][nj][2] + b0, acc[mi][nj][3] + b1);
            *(float2*)&C[(size_t)row * N + col] = v0;
            *(float2*)&C[(size_t)(row + 8) * N + col] = v1;
        }
    }
}

// ---------------------------------------------------------------------------
// Flash attention (causal), tf32 tensor-core, double-buffered K/V via cp.async.
// Grid: (S/64, B*H), 128 threads (4 warps), 64-query tile, 16 q per warp.
// ---------------------------------------------------------------------------
#define QP 68   /* pitch for Qs/Ks/Ps */
#define VP 72   /* pitch for Vs */
#define FSTAGES 2
#define KVSZ (64 * QP + 64 * VP)     /* one K+V stage, floats */
#define FLASH_SMEM ((2 * 64 * QP + FSTAGES * KVSZ) * (int)sizeof(float))

__global__ __launch_bounds__(128) void flash_tf32_kernel(
    const float* __restrict__ qkv, float* __restrict__ out)
{
    extern __shared__ float smf[];
    float* Qs  = smf;                   // 64*QP
    float* Ps  = Qs + 64 * QP;          // 64*QP
    float* KVs = Ps + 64 * QP;          // FSTAGES * (Ks 64*QP + Vs 64*VP)

    const int tid  = threadIdx.x;
    const int lane = tid & 31;
    const int warp = tid >> 5;     // 0..3, 16 queries each
    const int grp  = lane >> 2;
    const int qid  = lane & 3;

    const int bh = blockIdx.y;
    const int b  = bh / HEADS;
    const int h  = bh % HEADS;
    const int qt = gridDim.x - 1 - blockIdx.x;   // heavy tiles first
    const int q0 = qt * 64;
    const float scale = 0.125f;

    const float* qbase = qkv + (size_t)(b * SEQ) * NQKV + h * HDIM;
    const float* kbase = qbase + DIM;
    const float* vbase = qbase + 2 * DIM;

    const int lr = tid >> 4;            // 0..7
    const int lc = (tid & 15) * 4;      // 0..60

    // K/V tile loader (raw fp32, cp.async)
    auto loadKV = [&](int t) {
        float* ks = KVs + (t & 1) * KVSZ;
        float* vs = ks + 64 * QP;
        const int k0 = t * 64;
#pragma unroll
        for (int i = 0; i < 8; ++i) {
            const int row = lr + 8 * i;
            cp16(&ks[row * QP + lc], kbase + (size_t)(k0 + row) * NQKV + lc);
            cp16(&vs[row * VP + lc], vbase + (size_t)(k0 + row) * NQKV + lc);
        }
        CP_COMMIT();
    };

    // Load Q tile (raw)
#pragma unroll
    for (int i = 0; i < 8; ++i) {
        float4 v = *(const float4*)(qbase + (size_t)(q0 + lr + 8 * i) * NQKV + lc);
        *(float4*)&Qs[(lr + 8 * i) * QP + lc] = v;
    }
    loadKV(0);
    __syncthreads();   // Q visible to all warps

    // Q fragments, register-resident (tf32-rounded)
    unsigned qf[8][4];
#pragma unroll
    for (int ks = 0; ks < 8; ++ks) {
        const float* base = &Qs[(warp * 16 + grp) * QP + ks * 8 + qid];
        qf[ks][0] = ldcvt(base);
        qf[ks][1] = ldcvt(base + 8 * QP);
        qf[ks][2] = ldcvt(base + 4);
        qf[ks][3] = ldcvt(base + 8 * QP + 4);
    }

    float m0r = -INFINITY, m1r = -INFINITY, l0 = 0.f, l1 = 0.f;
    float o[8][4];
#pragma unroll
    for (int j = 0; j < 8; ++j)
#pragma unroll
        for (int r = 0; r < 4; ++r) o[j][r] = 0.f;

    const int ntiles = qt + 1;
    for (int t = 0; t < ntiles; ++t) {
        const int k0 = t * 64;
        CP_WAIT(0);              // tile t resident
        __syncthreads();         // all warps done with stage t^1
        if (t + 1 < ntiles) loadKV(t + 1);

        const float* Ks = KVs + (t & 1) * KVSZ;
        const float* Vs = Ks + 64 * QP;

        // S = Q K^T  (warp tile 16x64)
        float s[8][4];
#pragma unroll
        for (int j = 0; j < 8; ++j) {
            s[j][0] = s[j][1] = s[j][2] = s[j][3] = 0.f;
#pragma unroll
            for (int ks = 0; ks < 8; ++ks) {
                const float* base = &Ks[(j * 8 + grp) * QP + ks * 8 + qid];
                unsigned bf[2];
                bf[0] = ldcvt(base);
                bf[1] = ldcvt(base + 4);
                mma_tf32(s[j], qf[ks], bf);
            }
        }

        // scale + causal mask (diag tile only)
        const bool diag = (t == ntiles - 1);
        const int qi0 = q0 + warp * 16 + grp;
#pragma unroll
        for (int j = 0; j < 8; ++j) {
#pragma unroll
            for (int r = 0; r < 4; ++r) {
                float v = s[j][r] * scale;
                if (diag) {
                    const int kj = k0 + j * 8 + 2 * qid + (r & 1);
                    const int qi = qi0 + ((r >= 2) ? 8 : 0);
                    if (kj > qi) v = -INFINITY;
                }
                s[j][r] = v;
            }
        }

        // online softmax (rows grp and grp+8; 4-lane groups share a row)
        float mx0 = -INFINITY, mx1 = -INFINITY;
#pragma unroll
        for (int j = 0; j < 8; ++j) {
            mx0 = fmaxf(mx0, fmaxf(s[j][0], s[j][1]));
            mx1 = fmaxf(mx1, fmaxf(s[j][2], s[j][3]));
        }
        mx0 = fmaxf(mx0, __shfl_xor_sync(0xffffffffu, mx0, 1));
        mx0 = fmaxf(mx0, __shfl_xor_sync(0xffffffffu, mx0, 2));
        mx1 = fmaxf(mx1, __shfl_xor_sync(0xffffffffu, mx1, 1));
        mx1 = fmaxf(mx1, __shfl_xor_sync(0xffffffffu, mx1, 2));

        const float nm0 = fmaxf(m0r, mx0);
        const float nm1 = fmaxf(m1r, mx1);
        const float corr0 = __expf(m0r - nm0);
        const float corr1 = __expf(m1r - nm1);
        m0r = nm0; m1r = nm1;

        float sum0 = 0.f, sum1 = 0.f;
#pragma unroll
        for (int j = 0; j < 8; ++j) {
            s[j][0] = __expf(s[j][0] - nm0);
            s[j][1] = __expf(s[j][1] - nm0);
            s[j][2] = __expf(s[j][2] - nm1);
            s[j][3] = __expf(s[j][3] - nm1);
            sum0 += s[j][0] + s[j][1];
            sum1 += s[j][2] + s[j][3];
        }
        sum0 += __shfl_xor_sync(0xffffffffu, sum0, 1);
        sum0 += __shfl_xor_sync(0xffffffffu, sum0, 2);
        sum1 += __shfl_xor_sync(0xffffffffu, sum1, 1);
        sum1 += __shfl_xor_sync(0xffffffffu, sum1, 2);
        l0 = l0 * corr0 + sum0;
        l1 = l1 * corr1 + sum1;
#pragma unroll
        for (int j = 0; j < 8; ++j) {
            o[j][0] *= corr0; o[j][1] *= corr0;
            o[j][2] *= corr1; o[j][3] *= corr1;
        }

        // P fragments -> smem (C-layout -> A-layout round trip), warp-private
#pragma unroll
        for (int j = 0; j < 8; ++j) {
            float* p0 = &Ps[(warp * 16 + grp) * QP + j * 8 + 2 * qid];
            float* p1 = &Ps[(warp * 16 + grp + 8) * QP + j * 8 + 2 * qid];
            *(float2*)p0 = make_float2(s[j][0], s[j][1]);
            *(float2*)p1 = make_float2(s[j][2], s[j][3]);
        }
        __syncwarp();

        // O += P @ V
#pragma unroll
        for (int ks = 0; ks < 8; ++ks) {
            const float* abase = &Ps[(warp * 16 + grp) * QP + ks * 8 + qid];
            unsigned pf[4];
            pf[0] = ldcvt(abase);
            pf[1] = ldcvt(abase + 8 * QP);
            pf[2] = ldcvt(abase + 4);
            pf[3] = ldcvt(abase + 8 * QP + 4);
#pragma unroll
            for (int j = 0; j < 8; ++j) {
                const float* bbase = &Vs[(ks * 8 + qid) * VP + j * 8 + grp];
                unsigned bf[2];
                bf[0] = ldcvt(bbase);
                bf[1] = ldcvt(bbase + 4 * VP);
                mma_tf32(o[j], pf, bf);
            }
        }
    }

    // write normalized output
    const float inv0 = 1.0f / l0;
    const float inv1 = 1.0f / l1;
    const int row0 = q0 + warp * 16 + grp;
#pragma unroll
    for (int j = 0; j < 8; ++j) {
        const int col = h * HDIM + j * 8 + 2 * qid;
        *(float2*)&out[((size_t)(b * SEQ) + row0) * DIM + col] =
            make_float2(o[j][0] * inv0, o[j][1] * inv0);
        *(float2*)&out[((size_t)(b * SEQ) + row0 + 8) * DIM + col] =
            make_float2(o[j][2] * inv1, o[j][3] * inv1);
    }
}

// ---------------------------------------------------------------------------
extern "C" void kernel_launch(void* const* d_in, const int* in_sizes, int n_in,
                              void* d_out, int out_size)
{
    const float* x      = (const float*)d_in[0];   // [B,S,D]
    const float* qkv_w  = (const float*)d_in[1];   // [D, 3D]
    const float* qkv_b  = (const float*)d_in[2];   // [3D]
    const float* out_w  = (const float*)d_in[3];   // [D, D]
    const float* out_b  = (const float*)d_in[4];   // [D]
    float* out = (float*)d_out;

    float* qkv_buf = nullptr;
    float* att_buf = nullptr;
    cudaGetSymbolAddress((void**)&qkv_buf, g_qkv);
    cudaGetSymbolAddress((void**)&att_buf, g_att);

    cudaFuncSetAttribute(gemm_tf32_kernel,
                         cudaFuncAttributeMaxDynamicSharedMemorySize, GEMM_SMEM);
    cudaFuncSetAttribute(flash_tf32_kernel,
                         cudaFuncAttributeMaxDynamicSharedMemorySize, FLASH_SMEM);

    // 1) QKV projection: [4096,1024] @ [1024,3072] + b
    {
        dim3 grid(NQKV / BN, MROWS / BM);
        gemm_tf32_kernel<<<grid, 256, GEMM_SMEM>>>(x, qkv_w, qkv_b, qkv_buf,
                                                   MROWS, NQKV, DIM);
    }
    // 2) Causal flash attention (tf32 tensor cores)
    {
        dim3 grid(SEQ / 64, BATCH * HEADS);
        flash_tf32_kernel<<<grid, 128, FLASH_SMEM>>>(qkv_buf, att_buf);
    }
    // 3) Output projection: [4096,1024] @ [1024,1024] + b
    {
        dim3 grid(DIM / BN, MROWS / BM);
        gemm_tf32_kernel<<<grid, 256, GEMM_SMEM>>>(att_buf, out_w, out_b, out,
                                                   MROWS, DIM, DIM);
    }
}

// round 4
// speedup vs baseline: 1.2199x; 1.2199x over previous
#include <cuda_runtime.h>
#include <math.h>

#define BATCH 2
#define SEQ   2048
#define DIM   1024
#define HEADS 16
#define HDIM  64
#define MROWS (BATCH * SEQ)     /* 4096 */
#define NQKV  (3 * DIM)         /* 3072 */

// Scratch (device globals: no runtime allocation allowed)
__device__ float g_qkv[(size_t)MROWS * NQKV];   // ~50 MB
__device__ float g_att[(size_t)MROWS * DIM];    // ~17 MB

// ---------------------------------------------------------------------------
// helpers
// ---------------------------------------------------------------------------
__device__ __forceinline__ float tf32r(float x) {
    unsigned u;
    asm("cvt.rna.tf32.f32 %0, %1;" : "=r"(u) : "f"(x));
    return __uint_as_float(u);
}

__device__ __forceinline__ unsigned ldcvt(const float* p) {
    unsigned u;
    asm("cvt.rna.tf32.f32 %0, %1;" : "=r"(u) : "f"(*p));
    return u;
}

__device__ __forceinline__ void mma_tf32(float c[4], const unsigned a[4], const unsigned b[2]) {
    asm volatile(
        "mma.sync.aligned.m16n8k8.row.col.f32.tf32.tf32.f32 "
        "{%0,%1,%2,%3}, {%4,%5,%6,%7}, {%8,%9}, {%0,%1,%2,%3};\n"
        : "+f"(c[0]), "+f"(c[1]), "+f"(c[2]), "+f"(c[3])
        : "r"(a[0]), "r"(a[1]), "r"(a[2]), "r"(a[3]), "r"(b[0]), "r"(b[1]));
}

__device__ __forceinline__ void cp16(float* s, const float* g) {
    unsigned sa = (unsigned)__cvta_generic_to_shared(s);
    asm volatile("cp.async.cg.shared.global [%0], [%1], 16;\n" :: "r"(sa), "l"(g));
}
#define CP_COMMIT() asm volatile("cp.async.commit_group;\n" ::: "memory")
#define CP_WAIT(N)  asm volatile("cp.async.wait_group %0;\n" :: "n"(N) : "memory")

// ---------------------------------------------------------------------------
// TF32 GEMM: C[M,N] = A[M,K] @ W[K,N] + bias[N]
// Block 128x128x32, 8 warps (2x4), warp tile 64x32, mma m16n8k8.
// 2-stage cp.async ring, 2 CTAs/SM (regs capped at 128).
// ---------------------------------------------------------------------------
#define BM 128
#define BN 128
#define BK 32
#define APITCH 36    /* conflict-free A-frag loads */
#define BPITCH 132   /* conflict-free B-frag loads */
#define GSTAGES 2
#define ASZ (BM * APITCH)
#define BSZ (BK * BPITCH)
#define GEMM_SMEM ((GSTAGES * (ASZ + BSZ)) * (int)sizeof(float))   /* 70656 B */

__global__ __launch_bounds__(256, 2) void gemm_tf32_kernel(
    const float* __restrict__ A, const float* __restrict__ W,
    const float* __restrict__ bias, float* __restrict__ C,
    int M, int N, int K)
{
    extern __shared__ float dyn[];
    float* As = dyn;                     // [GSTAGES][BM][APITCH]
    float* Bs = dyn + GSTAGES * ASZ;     // [GSTAGES][BK][BPITCH]

    const int tid  = threadIdx.x;
    const int lane = tid & 31;
    const int warp = tid >> 5;
    const int wr   = warp >> 2;          // 0..1
    const int wc   = warp & 3;           // 0..3
    const int grp  = lane >> 2;          // 0..7
    const int qid  = lane & 3;           // 0..3

    const int m0 = blockIdx.y * BM;
    const int n0 = blockIdx.x * BN;

    const int arow = tid >> 3;           // 0..31 (rows arow + 32*i)
    const int akc  = (tid & 7) * 4;      // k offset within BK
    const int brow = tid >> 5;           // 0..7  (rows brow + 8*i)
    const int bnc  = (tid & 31) * 4;     // n offset within BN

    const int T = K / BK;

    // tile loader: global -> smem stage (raw fp32 via cp.async)
    auto loadtile = [&](int t) {
        float* as = As + (t & 1) * ASZ;
        float* bs = Bs + (t & 1) * BSZ;
        const int k0 = t * BK;
#pragma unroll
        for (int i = 0; i < 4; ++i)
            cp16(&as[(arow + 32 * i) * APITCH + akc],
                 A + (size_t)(m0 + arow + 32 * i) * K + k0 + akc);
#pragma unroll
        for (int i = 0; i < 4; ++i)
            cp16(&bs[(brow + 8 * i) * BPITCH + bnc],
                 W + (size_t)(k0 + brow + 8 * i) * N + n0 + bnc);
        CP_COMMIT();
    };

    float acc[4][4][4];
#pragma unroll
    for (int mi = 0; mi < 4; ++mi)
#pragma unroll
        for (int nj = 0; nj < 4; ++nj)
#pragma unroll
            for (int r = 0; r < 4; ++r) acc[mi][nj][r] = 0.f;

    loadtile(0);

    for (int t = 0; t < T; ++t) {
        CP_WAIT(0);              // tile t resident
        __syncthreads();         // all warps done with stage t^1 (tile t-1)
        if (t + 1 < T) loadtile(t + 1);

        const float* as = As + (t & 1) * ASZ;
        const float* bs = Bs + (t & 1) * BSZ;

#pragma unroll
        for (int ks = 0; ks < 4; ++ks) {
            unsigned af[4][4], bf[4][2];
#pragma unroll
            for (int mi = 0; mi < 4; ++mi) {
                const float* base = &as[(wr * 64 + mi * 16 + grp) * APITCH + ks * 8 + qid];
                af[mi][0] = ldcvt(base);
                af[mi][1] = ldcvt(base + 8 * APITCH);
                af[mi][2] = ldcvt(base + 4);
                af[mi][3] = ldcvt(base + 8 * APITCH + 4);
            }
#pragma unroll
            for (int nj = 0; nj < 4; ++nj) {
                const float* base = &bs[(ks * 8 + qid) * BPITCH + wc * 32 + nj * 8 + grp];
                bf[nj][0] = ldcvt(base);
                bf[nj][1] = ldcvt(base + 4 * BPITCH);
            }
#pragma unroll
            for (int mi = 0; mi < 4; ++mi)
#pragma unroll
                for (int nj = 0; nj < 4; ++nj)
                    mma_tf32(acc[mi][nj], af[mi], bf[nj]);
        }
        __syncthreads();         // done reading stage t before iter t+1 rewrites t^1? (t+1 writes stage (t+1)&1 = t^1 — protected above; this sync guards stage t for iter t+2's load issued at t+1)
    }

    // epilogue: bias + store
#pragma unroll
    for (int mi = 0; mi < 4; ++mi) {
#pragma unroll
        for (int nj = 0; nj < 4; ++nj) {
            const int row = m0 + wr * 64 + mi * 16 + grp;
            const int col = n0 + wc * 32 + nj * 8 + 2 * qid;
            const float b0 = bias[col];
            const float b1 = bias[col + 1];
            float2 v0 = make_float2(acc[mi][nj][0] + b0, acc[mi][nj][1] + b1);
            float2 v1 = make_float2(acc[mi][nj][2] + b0, acc[mi][nj][3] + b1);
            *(float2*)&C[(size_t)row * N + col] = v0;
            *(float2*)&C[(size_t)(row + 8) * N + col] = v1;
        }
    }
}

// ---------------------------------------------------------------------------
// Flash attention (causal), tf32 tensor-core (R2 proven config: 69KB, 3 CTA/SM).
// Grid: (S/64, B*H), 128 threads (4 warps), 64-query tile, 16 q per warp.
// ---------------------------------------------------------------------------
#define QP 68   /* pitch for Qs/Ks/Ps: conflict-free frag loads */
#define VP 72   /* pitch for Vs */
#define FLASH_SMEM ((3 * 64 * QP + 64 * VP) * (int)sizeof(float))  /* 70656 B */

__global__ __launch_bounds__(128) void flash_tf32_kernel(
    const float* __restrict__ qkv, float* __restrict__ out)
{
    extern __shared__ float smf[];
    float* Qs = smf;               // 64*QP
    float* Ks = Qs + 64 * QP;      // 64*QP
    float* Ps = Ks + 64 * QP;      // 64*QP
    float* Vs = Ps + 64 * QP;      // 64*VP

    const int tid  = threadIdx.x;
    const int lane = tid & 31;
    const int warp = tid >> 5;     // 0..3, 16 queries each
    const int grp  = lane >> 2;
    const int qid  = lane & 3;

    const int bh = blockIdx.y;
    const int b  = bh / HEADS;
    const int h  = bh % HEADS;
    const int qt = gridDim.x - 1 - blockIdx.x;   // heavy tiles first
    const int q0 = qt * 64;
    const float scale = 0.125f;

    const float* qbase = qkv + (size_t)(b * SEQ) * NQKV + h * HDIM;
    const float* kbase = qbase + DIM;
    const float* vbase = qbase + 2 * DIM;

    const int lr = tid >> 4;            // 0..7
    const int lc = (tid & 15) * 4;      // 0..60

    // Load Q tile (tf32-rounded)
#pragma unroll
    for (int i = 0; i < 8; ++i) {
        float4 v = *(const float4*)(qbase + (size_t)(q0 + lr + 8 * i) * NQKV + lc);
        *(float4*)&Qs[(lr + 8 * i) * QP + lc] =
            make_float4(tf32r(v.x), tf32r(v.y), tf32r(v.z), tf32r(v.w));
    }
    __syncthreads();

    // Q fragments, register-resident for whole kernel
    unsigned qf[8][4];
#pragma unroll
    for (int ks = 0; ks < 8; ++ks) {
        const float* base = &Qs[(warp * 16 + grp) * QP + ks * 8 + qid];
        qf[ks][0] = __float_as_uint(base[0]);
        qf[ks][1] = __float_as_uint(base[8 * QP]);
        qf[ks][2] = __float_as_uint(base[4]);
        qf[ks][3] = __float_as_uint(base[8 * QP + 4]);
    }

    float m0r = -INFINITY, m1r = -INFINITY, l0 = 0.f, l1 = 0.f;
    float o[8][4];
#pragma unroll
    for (int j = 0; j < 8; ++j)
#pragma unroll
        for (int r = 0; r < 4; ++r) o[j][r] = 0.f;

    const int ntiles = qt + 1;
    for (int t = 0; t < ntiles; ++t) {
        const int k0 = t * 64;
        __syncthreads();
        // Load K,V tiles (tf32-rounded)
#pragma unroll
        for (int i = 0; i < 8; ++i) {
            const int row = lr + 8 * i;
            float4 kv = *(const float4*)(kbase + (size_t)(k0 + row) * NQKV + lc);
            float4 vv = *(const float4*)(vbase + (size_t)(k0 + row) * NQKV + lc);
            *(float4*)&Ks[row * QP + lc] =
                make_float4(tf32r(kv.x), tf32r(kv.y), tf32r(kv.z), tf32r(kv.w));
            *(float4*)&Vs[row * VP + lc] =
                make_float4(tf32r(vv.x), tf32r(vv.y), tf32r(vv.z), tf32r(vv.w));
        }
        __syncthreads();

        // S = Q K^T  (warp tile 16x64)
        float s[8][4];
#pragma unroll
        for (int j = 0; j < 8; ++j) {
            s[j][0] = s[j][1] = s[j][2] = s[j][3] = 0.f;
#pragma unroll
            for (int ks = 0; ks < 8; ++ks) {
                const float* base = &Ks[(j * 8 + grp) * QP + ks * 8 + qid];
                unsigned bf[2];
                bf[0] = __float_as_uint(base[0]);
                bf[1] = __float_as_uint(base[4]);
                mma_tf32(s[j], qf[ks], bf);
            }
        }

        // scale + causal mask (diag tile only)
        const bool diag = (t == ntiles - 1);
        const int qi0 = q0 + warp * 16 + grp;
#pragma unroll
        for (int j = 0; j < 8; ++j) {
#pragma unroll
            for (int r = 0; r < 4; ++r) {
                float v = s[j][r] * scale;
                if (diag) {
                    const int kj = k0 + j * 8 + 2 * qid + (r & 1);
                    const int qi = qi0 + ((r >= 2) ? 8 : 0);
                    if (kj > qi) v = -INFINITY;
                }
                s[j][r] = v;
            }
        }

        // online softmax (rows grp and grp+8; 4-lane groups share a row)
        float mx0 = -INFINITY, mx1 = -INFINITY;
#pragma unroll
        for (int j = 0; j < 8; ++j) {
            mx0 = fmaxf(mx0, fmaxf(s[j][0], s[j][1]));
            mx1 = fmaxf(mx1, fmaxf(s[j][2], s[j][3]));
        }
        mx0 = fmaxf(mx0, __shfl_xor_sync(0xffffffffu, mx0, 1));
        mx0 = fmaxf(mx0, __shfl_xor_sync(0xffffffffu, mx0, 2));
        mx1 = fmaxf(mx1, __shfl_xor_sync(0xffffffffu, mx1, 1));
        mx1 = fmaxf(mx1, __shfl_xor_sync(0xffffffffu, mx1, 2));

        const float nm0 = fmaxf(m0r, mx0);
        const float nm1 = fmaxf(m1r, mx1);
        const float corr0 = __expf(m0r - nm0);
        const float corr1 = __expf(m1r - nm1);
        m0r = nm0; m1r = nm1;

        float sum0 = 0.f, sum1 = 0.f;
#pragma unroll
        for (int j = 0; j < 8; ++j) {
            s[j][0] = __expf(s[j][0] - nm0);
            s[j][1] = __expf(s[j][1] - nm0);
            s[j][2] = __expf(s[j][2] - nm1);
            s[j][3] = __expf(s[j][3] - nm1);
            sum0 += s[j][0] + s[j][1];
            sum1 += s[j][2] + s[j][3];
        }
        sum0 += __shfl_xor_sync(0xffffffffu, sum0, 1);
        sum0 += __shfl_xor_sync(0xffffffffu, sum0, 2);
        sum1 += __shfl_xor_sync(0xffffffffu, sum1, 1);
        sum1 += __shfl_xor_sync(0xffffffffu, sum1, 2);
        l0 = l0 * corr0 + sum0;
        l1 = l1 * corr1 + sum1;
#pragma unroll
        for (int j = 0; j < 8; ++j) {
            o[j][0] *= corr0; o[j][1] *= corr0;
            o[j][2] *= corr1; o[j][3] *= corr1;
        }

        // P fragments -> smem (C-layout -> A-layout round trip), warp-private
#pragma unroll
        for (int j = 0; j < 8; ++j) {
            float* p0 = &Ps[(warp * 16 + grp) * QP + j * 8 + 2 * qid];
            float* p1 = &Ps[(warp * 16 + grp + 8) * QP + j * 8 + 2 * qid];
            *(float2*)p0 = make_float2(tf32r(s[j][0]), tf32r(s[j][1]));
            *(float2*)p1 = make_float2(tf32r(s[j][2]), tf32r(s[j][3]));
        }
        __syncwarp();

        // O += P @ V
#pragma unroll
        for (int ks = 0; ks < 8; ++ks) {
            const float* abase = &Ps[(warp * 16 + grp) * QP + ks * 8 + qid];
            unsigned pf[4];
            pf[0] = __float_as_uint(abase[0]);
            pf[1] = __float_as_uint(abase[8 * QP]);
            pf[2] = __float_as_uint(abase[4]);
            pf[3] = __float_as_uint(abase[8 * QP + 4]);
#pragma unroll
            for (int j = 0; j < 8; ++j) {
                const float* bbase = &Vs[(ks * 8 + qid) * VP + j * 8 + grp];
                unsigned bf[2];
                bf[0] = __float_as_uint(bbase[0]);
                bf[1] = __float_as_uint(bbase[4 * VP]);
                mma_tf32(o[j], pf, bf);
            }
        }
    }

    // write normalized output
    const float inv0 = 1.0f / l0;
    const float inv1 = 1.0f / l1;
    const int row0 = q0 + warp * 16 + grp;
#pragma unroll
    for (int j = 0; j < 8; ++j) {
        const int col = h * HDIM + j * 8 + 2 * qid;
        *(float2*)&out[((size_t)(b * SEQ) + row0) * DIM + col] =
            make_float2(o[j][0] * inv0, o[j][1] * inv0);
        *(float2*)&out[((size_t)(b * SEQ) + row0 + 8) * DIM + col] =
            make_float2(o[j][2] * inv1, o[j][3] * inv1);
    }
}

// ---------------------------------------------------------------------------
extern "C" void kernel_launch(void* const* d_in, const int* in_sizes, int n_in,
                              void* d_out, int out_size)
{
    const float* x      = (const float*)d_in[0];   // [B,S,D]
    const float* qkv_w  = (const float*)d_in[1];   // [D, 3D]
    const float* qkv_b  = (const float*)d_in[2];   // [3D]
    const float* out_w  = (const float*)d_in[3];   // [D, D]
    const float* out_b  = (const float*)d_in[4];   // [D]
    float* out = (float*)d_out;

    float* qkv_buf = nullptr;
    float* att_buf = nullptr;
    cudaGetSymbolAddress((void**)&qkv_buf, g_qkv);
    cudaGetSymbolAddress((void**)&att_buf, g_att);

    cudaFuncSetAttribute(gemm_tf32_kernel,
                         cudaFuncAttributeMaxDynamicSharedMemorySize, GEMM_SMEM);
    cudaFuncSetAttribute(flash_tf32_kernel,
                         cudaFuncAttributeMaxDynamicSharedMemorySize, FLASH_SMEM);

    // 1) QKV projection: [4096,1024] @ [1024,3072] + b
    {
        dim3 grid(NQKV / BN, MROWS / BM);
        gemm_tf32_kernel<<<grid, 256, GEMM_SMEM>>>(x, qkv_w, qkv_b, qkv_buf,
                                                   MROWS, NQKV, DIM);
    }
    // 2) Causal flash attention (tf32 tensor cores)
    {
        dim3 grid(SEQ / 64, BATCH * HEADS);
        flash_tf32_kernel<<<grid, 128, FLASH_SMEM>>>(qkv_buf, att_buf);
    }
    // 3) Output projection: [4096,1024] @ [1024,1024] + b
    {
        dim3 grid(DIM / BN, MROWS / BM);
        gemm_tf32_kernel<<<grid, 256, GEMM_SMEM>>>(att_buf, out_w, out_b, out,
                                                   MROWS, DIM, DIM);
    }
}